// round 1
// baseline (speedup 1.0000x reference)
#include <cuda_runtime.h>

#define SLOPE 0.2f
#define BATCH 262144

__device__ __forceinline__ float leaky(float v) {
    return v > 0.0f ? v : SLOPE * v;
}

__device__ __forceinline__ float fast_tanh(float x) {
    // clamp to avoid inf/inf -> NaN; tanh saturates long before |x|=10
    x = fminf(fmaxf(x, -10.0f), 10.0f);
    float e = __expf(2.0f * x);
    return __fdividef(e - 1.0f, e + 1.0f);
}

__global__ void __launch_bounds__(256)
minigen_kernel(const float4* __restrict__ x,
               const float* __restrict__ w_enc1, const float* __restrict__ b_enc1,
               const float* __restrict__ w_bneck, const float* __restrict__ b_bneck,
               const float* __restrict__ w_dec1, const float* __restrict__ b_dec1,
               const float* __restrict__ w_out,  const float* __restrict__ b_out,
               float4* __restrict__ out)
{
    // ---- stage all weights/biases in shared memory (broadcast reads) ----
    __shared__ float s_we[24], s_be[4];
    __shared__ float s_wb[96], s_bb[8];
    __shared__ float s_wd[96], s_bd[4];
    __shared__ float s_wo[24], s_bo[2];

    int t = threadIdx.x;
    if (t < 24)  s_we[t] = w_enc1[t];
    if (t < 4)   s_be[t] = b_enc1[t];
    if (t < 96)  s_wb[t] = w_bneck[t];
    if (t < 8)   s_bb[t] = b_bneck[t];
    if (t >= 96 && t < 192) s_wd[t - 96] = w_dec1[t - 96];
    if (t >= 192 && t < 196) s_bd[t - 192] = b_dec1[t - 192];
    if (t >= 196 && t < 220) s_wo[t - 196] = w_out[t - 196];
    if (t >= 220 && t < 222) s_bo[t - 220] = b_out[t - 220];
    __syncthreads();

    int i = blockIdx.x * blockDim.x + threadIdx.x;   // sample index

    // ---- load x: 32 contiguous floats == exactly one 128B line per sample ----
    float X[32];   // X[ci*16 + l]
    {
        const float4* xp = x + (size_t)i * 8;
        #pragma unroll
        for (int q = 0; q < 8; q++) {
            float4 v = xp[q];
            X[q * 4 + 0] = v.x; X[q * 4 + 1] = v.y;
            X[q * 4 + 2] = v.z; X[q * 4 + 3] = v.w;
        }
    }

    // ---- enc1: conv1d(C2->C4, k3, stride2, pad1) + leaky -> E[4][8] ----
    float E[4][8];
    #pragma unroll
    for (int c = 0; c < 4; c++) {
        float w00 = s_we[c*6 + 0], w01 = s_we[c*6 + 1], w02 = s_we[c*6 + 2];
        float w10 = s_we[c*6 + 3], w11 = s_we[c*6 + 4], w12 = s_we[c*6 + 5];
        float b = s_be[c];
        #pragma unroll
        for (int l = 0; l < 8; l++) {
            float a = b;
            int p = 2 * l;
            if (l > 0) a += w00 * X[p - 1] + w10 * X[16 + p - 1];
            a += w01 * X[p]     + w11 * X[16 + p];
            a += w02 * X[p + 1] + w12 * X[16 + p + 1];
            E[c][l] = leaky(a);
        }
    }

    // ---- bneck: conv1d(C4->C8, k3, stride2, pad1) + leaky -> Bn[8][4] ----
    float Bn[8][4];
    #pragma unroll
    for (int co = 0; co < 8; co++) {
        float wk[4][3];
        #pragma unroll
        for (int ci = 0; ci < 4; ci++)
            #pragma unroll
            for (int k = 0; k < 3; k++)
                wk[ci][k] = s_wb[co*12 + ci*3 + k];
        float b = s_bb[co];
        #pragma unroll
        for (int l = 0; l < 4; l++) {
            float a = b;
            int p = 2 * l;
            #pragma unroll
            for (int ci = 0; ci < 4; ci++) {
                if (l > 0) a += wk[ci][0] * E[ci][p - 1];
                a += wk[ci][1] * E[ci][p] + wk[ci][2] * E[ci][p + 1];
            }
            Bn[co][l] = leaky(a);
        }
    }

    // ---- dec1: upsample2(Bn) then conv1d(C8->C4, k3, s1, pad1) + leaky, + skip E
    // upsample folding: up[j] = Bn[j>>1]
    //   l==0      : (w1+w2)*Bn[0]
    //   l even>0  : w0*Bn[l/2-1] + (w1+w2)*Bn[l/2]
    //   l odd<7   : (w0+w1)*Bn[(l-1)/2] + w2*Bn[(l+1)/2]
    //   l==7      : (w0+w1)*Bn[3]
    float S[4][8];
    #pragma unroll
    for (int c = 0; c < 4; c++) {
        float w0s[8], w2s[8], w01s[8], w12s[8];
        #pragma unroll
        for (int ci = 0; ci < 8; ci++) {
            float w0 = s_wd[c*24 + ci*3 + 0];
            float w1 = s_wd[c*24 + ci*3 + 1];
            float w2 = s_wd[c*24 + ci*3 + 2];
            w0s[ci] = w0; w2s[ci] = w2;
            w01s[ci] = w0 + w1; w12s[ci] = w1 + w2;
        }
        float b = s_bd[c];
        #pragma unroll
        for (int l = 0; l < 8; l++) {
            float a = b;
            #pragma unroll
            for (int ci = 0; ci < 8; ci++) {
                if (l == 0)            a += w12s[ci] * Bn[ci][0];
                else if (l == 7)       a += w01s[ci] * Bn[ci][3];
                else if ((l & 1) == 0) a += w0s[ci]  * Bn[ci][l/2 - 1] + w12s[ci] * Bn[ci][l/2];
                else                   a += w01s[ci] * Bn[ci][(l-1)/2] + w2s[ci]  * Bn[ci][(l+1)/2];
            }
            S[c][l] = leaky(a) + E[c][l];
        }
    }

    // ---- out: upsample2(S) then conv1d(C4->C2, k3, s1, pad1) + tanh -> O[2][16]
    float O[32];
    #pragma unroll
    for (int c = 0; c < 2; c++) {
        float w0s[4], w2s[4], w01s[4], w12s[4];
        #pragma unroll
        for (int ci = 0; ci < 4; ci++) {
            float w0 = s_wo[c*12 + ci*3 + 0];
            float w1 = s_wo[c*12 + ci*3 + 1];
            float w2 = s_wo[c*12 + ci*3 + 2];
            w0s[ci] = w0; w2s[ci] = w2;
            w01s[ci] = w0 + w1; w12s[ci] = w1 + w2;
        }
        float b = s_bo[c];
        #pragma unroll
        for (int l = 0; l < 16; l++) {
            float a = b;
            #pragma unroll
            for (int ci = 0; ci < 4; ci++) {
                if (l == 0)            a += w12s[ci] * S[ci][0];
                else if (l == 15)      a += w01s[ci] * S[ci][7];
                else if ((l & 1) == 0) a += w0s[ci]  * S[ci][l/2 - 1] + w12s[ci] * S[ci][l/2];
                else                   a += w01s[ci] * S[ci][(l-1)/2] + w2s[ci]  * S[ci][(l+1)/2];
            }
            O[c*16 + l] = fast_tanh(a);
        }
    }

    // ---- store: 32 contiguous floats == one 128B line per sample ----
    {
        float4* op = out + (size_t)i * 8;
        #pragma unroll
        for (int q = 0; q < 8; q++) {
            float4 v;
            v.x = O[q*4 + 0]; v.y = O[q*4 + 1];
            v.z = O[q*4 + 2]; v.w = O[q*4 + 3];
            op[q] = v;
        }
    }
}

extern "C" void kernel_launch(void* const* d_in, const int* in_sizes, int n_in,
                              void* d_out, int out_size) {
    const float4* x      = (const float4*)d_in[0];
    const float* w_enc1  = (const float*)d_in[1];
    const float* b_enc1  = (const float*)d_in[2];
    const float* w_bneck = (const float*)d_in[3];
    const float* b_bneck = (const float*)d_in[4];
    const float* w_dec1  = (const float*)d_in[5];
    const float* b_dec1  = (const float*)d_in[6];
    const float* w_out   = (const float*)d_in[7];
    const float* b_out   = (const float*)d_in[8];
    float4* out = (float4*)d_out;

    int B = in_sizes[0] / 32;            // samples
    int threads = 256;
    int blocks = (B + threads - 1) / threads;
    minigen_kernel<<<blocks, threads>>>(x, w_enc1, b_enc1, w_bneck, b_bneck,
                                        w_dec1, b_dec1, w_out, b_out, out);
}

// round 2
// speedup vs baseline: 1.1119x; 1.1119x over previous
#include <cuda_runtime.h>

typedef unsigned long long u64;

// ---- packed f32x2 helpers (sm_103a packed fp32 pipe) ----
__device__ __forceinline__ u64 pk2(float l, float h) {
    u64 r; asm("mov.b64 %0, {%1,%2};" : "=l"(r) : "f"(l), "f"(h)); return r;
}
__device__ __forceinline__ u64 pkb(float w) { return pk2(w, w); }
__device__ __forceinline__ void upk(u64 v, float& l, float& h) {
    asm("mov.b64 {%0,%1}, %2;" : "=f"(l), "=f"(h) : "l"(v));
}
__device__ __forceinline__ u64 fma2(u64 a, u64 b, u64 c) {
    u64 d; asm("fma.rn.f32x2 %0, %1, %2, %3;" : "=l"(d) : "l"(a), "l"(b), "l"(c)); return d;
}
__device__ __forceinline__ u64 add2(u64 a, u64 b) {
    u64 d; asm("add.rn.f32x2 %0, %1, %2;" : "=l"(d) : "l"(a), "l"(b)); return d;
}
__device__ __forceinline__ u64 mul2(u64 a, u64 b) {
    u64 d; asm("mul.rn.f32x2 %0, %1, %2;" : "=l"(d) : "l"(a), "l"(b)); return d;
}

// packed constants (both lanes same fp32 bit pattern)
#define KDUP(bits) ((((u64)(bits)) << 32) | (u64)(bits))
static constexpr u64 K06     = KDUP(0x3F19999Au);  // 0.6f
static constexpr u64 K04     = KDUP(0x3ECCCCCDu);  // 0.4f
static constexpr u64 K1      = KDUP(0x3F800000u);  // 1.0f
static constexpr u64 KM2     = KDUP(0xC0000000u);  // -2.0f
static constexpr u64 K2L2E   = KDUP(0x4038AA3Bu);  // 2*log2(e)
static constexpr u64 KABS    = 0x7FFFFFFF7FFFFFFFull;
static constexpr u64 KSIGN   = 0x8000000080000000ull;

// leaky_relu(x, 0.2) == 0.6*x + 0.4*|x|   (branch-free, fully packed)
__device__ __forceinline__ u64 leaky2(u64 v) {
    return fma2(v & KABS, K04, mul2(v, K06));
}

// tanh(x) = sign(x) * (1 - 2/(exp(2|x|)+1)); overflow-safe (rcp(inf)=0)
__device__ __forceinline__ u64 tanh2(u64 v) {
    u64 a = v & KABS;
    u64 s = v & KSIGN;
    u64 t = mul2(a, K2L2E);
    float tl, th; upk(t, tl, th);
    float el, eh;
    asm("ex2.approx.f32 %0, %1;" : "=f"(el) : "f"(tl));
    asm("ex2.approx.f32 %0, %1;" : "=f"(eh) : "f"(th));
    u64 d = add2(pk2(el, eh), K1);
    float dl, dh; upk(d, dl, dh);
    float rl, rh;
    asm("rcp.approx.f32 %0, %1;" : "=f"(rl) : "f"(dl));
    asm("rcp.approx.f32 %0, %1;" : "=f"(rh) : "f"(dh));
    u64 w = fma2(pk2(rl, rh), KM2, K1);   // 1 - 2r
    return w ^ s;
}

__global__ void __launch_bounds__(128)
minigen_kernel(const float4* __restrict__ x,
               const float* __restrict__ w_enc1, const float* __restrict__ b_enc1,
               const float* __restrict__ w_bneck, const float* __restrict__ b_bneck,
               const float* __restrict__ w_dec1, const float* __restrict__ b_dec1,
               const float* __restrict__ w_out,  const float* __restrict__ b_out,
               float4* __restrict__ out)
{
    __shared__ float s_we[24], s_be[4];
    __shared__ float s_wb[96], s_bb[8];
    __shared__ float s_wdf[128], s_bd[4];   // dec1 folded: {w0, w2, w0+w1, w1+w2} per (c,ci)
    __shared__ float s_wof[32],  s_bo[2];   // out  folded

    int t = threadIdx.x;
    if (t < 24) s_we[t] = w_enc1[t];
    if (t < 96) s_wb[t] = w_bneck[t];
    if (t < 4)  { s_be[t] = b_enc1[t]; s_bd[t] = b_dec1[t]; }
    if (t < 8)  s_bb[t] = b_bneck[t];
    if (t < 2)  s_bo[t] = b_out[t];
    if (t < 32) {   // dec1 fold: t = c*8 + ci
        float w0 = w_dec1[t*3], w1 = w_dec1[t*3+1], w2 = w_dec1[t*3+2];
        s_wdf[t*4+0] = w0; s_wdf[t*4+1] = w2;
        s_wdf[t*4+2] = w0 + w1; s_wdf[t*4+3] = w1 + w2;
    }
    if (t < 8) {    // out fold: t = c*4 + ci
        float w0 = w_out[t*3], w1 = w_out[t*3+1], w2 = w_out[t*3+2];
        s_wof[t*4+0] = w0; s_wof[t*4+1] = w2;
        s_wof[t*4+2] = w0 + w1; s_wof[t*4+3] = w1 + w2;
    }
    __syncthreads();

    int i = blockIdx.x * blockDim.x + threadIdx.x;   // sample-pair index

    // ---- load 2 samples (2 * 128B contiguous lines), pack across samples ----
    u64 X2[32];
    {
        const float4* xp = x + (size_t)i * 16;
        float A[32], Bv[32];
        #pragma unroll
        for (int q = 0; q < 8; q++) {
            float4 va = xp[q];
            A[q*4+0] = va.x; A[q*4+1] = va.y; A[q*4+2] = va.z; A[q*4+3] = va.w;
        }
        #pragma unroll
        for (int q = 0; q < 8; q++) {
            float4 vb = xp[8 + q];
            Bv[q*4+0] = vb.x; Bv[q*4+1] = vb.y; Bv[q*4+2] = vb.z; Bv[q*4+3] = vb.w;
        }
        #pragma unroll
        for (int j = 0; j < 32; j++) X2[j] = pk2(A[j], Bv[j]);
    }

    // ---- enc1: conv(C2->C4, k3, s2, p1) + leaky -> E[4][8] ----
    u64 E[4][8];
    #pragma unroll
    for (int c = 0; c < 4; c++) {
        u64 w00 = pkb(s_we[c*6+0]), w01 = pkb(s_we[c*6+1]), w02 = pkb(s_we[c*6+2]);
        u64 w10 = pkb(s_we[c*6+3]), w11 = pkb(s_we[c*6+4]), w12 = pkb(s_we[c*6+5]);
        u64 b2 = pkb(s_be[c]);
        #pragma unroll
        for (int l = 0; l < 8; l++) {
            int p = 2 * l;
            u64 a = b2;
            if (l > 0) { a = fma2(w00, X2[p-1], a); a = fma2(w10, X2[16+p-1], a); }
            a = fma2(w01, X2[p],     a); a = fma2(w11, X2[16+p],   a);
            a = fma2(w02, X2[p+1],   a); a = fma2(w12, X2[16+p+1], a);
            E[c][l] = leaky2(a);
        }
    }

    // ---- bneck: conv(C4->C8, k3, s2, p1) + leaky -> Bn[8][4] ----
    u64 Bn[8][4];
    #pragma unroll
    for (int co = 0; co < 8; co++) {
        u64 wk[4][3];
        #pragma unroll
        for (int ci = 0; ci < 4; ci++)
            #pragma unroll
            for (int k = 0; k < 3; k++)
                wk[ci][k] = pkb(s_wb[co*12 + ci*3 + k]);
        u64 b2 = pkb(s_bb[co]);
        #pragma unroll
        for (int l = 0; l < 4; l++) {
            int p = 2 * l;
            u64 a = b2;
            #pragma unroll
            for (int ci = 0; ci < 4; ci++) {
                if (l > 0) a = fma2(wk[ci][0], E[ci][p-1], a);
                a = fma2(wk[ci][1], E[ci][p], a);
                a = fma2(wk[ci][2], E[ci][p+1], a);
            }
            Bn[co][l] = leaky2(a);
        }
    }

    // ---- dec1: upsample2 + conv(C8->C4, k3, s1, p1) + leaky, skip added in-place into E
    #pragma unroll
    for (int c = 0; c < 4; c++) {
        u64 acc[8];
        u64 b2 = pkb(s_bd[c]);
        #pragma unroll
        for (int l = 0; l < 8; l++) acc[l] = b2;
        #pragma unroll
        for (int ci = 0; ci < 8; ci++) {
            const float* wf = &s_wdf[(c*8 + ci) * 4];
            u64 w0 = pkb(wf[0]), w2 = pkb(wf[1]), w01 = pkb(wf[2]), w12 = pkb(wf[3]);
            u64 q0 = Bn[ci][0], q1 = Bn[ci][1], q2 = Bn[ci][2], q3 = Bn[ci][3];
            acc[0] = fma2(w12, q0, acc[0]);
            acc[1] = fma2(w01, q0, acc[1]); acc[1] = fma2(w2,  q1, acc[1]);
            acc[2] = fma2(w0,  q0, acc[2]); acc[2] = fma2(w12, q1, acc[2]);
            acc[3] = fma2(w01, q1, acc[3]); acc[3] = fma2(w2,  q2, acc[3]);
            acc[4] = fma2(w0,  q1, acc[4]); acc[4] = fma2(w12, q2, acc[4]);
            acc[5] = fma2(w01, q2, acc[5]); acc[5] = fma2(w2,  q3, acc[5]);
            acc[6] = fma2(w0,  q2, acc[6]); acc[6] = fma2(w12, q3, acc[6]);
            acc[7] = fma2(w01, q3, acc[7]);
        }
        #pragma unroll
        for (int l = 0; l < 8; l++)
            E[c][l] = add2(leaky2(acc[l]), E[c][l]);   // skip connection
    }

    // ---- out: upsample2 + conv(C4->C2, k3, s1, p1) + tanh -> O2[2][16] ----
    u64 O2[32];
    #pragma unroll
    for (int c = 0; c < 2; c++) {
        u64 acc[16];
        u64 b2 = pkb(s_bo[c]);
        #pragma unroll
        for (int l = 0; l < 16; l++) acc[l] = b2;
        #pragma unroll
        for (int ci = 0; ci < 4; ci++) {
            const float* wf = &s_wof[(c*4 + ci) * 4];
            u64 w0 = pkb(wf[0]), w2 = pkb(wf[1]), w01 = pkb(wf[2]), w12 = pkb(wf[3]);
            acc[0]  = fma2(w12, E[ci][0], acc[0]);
            #pragma unroll
            for (int l = 1; l < 15; l++) {
                if ((l & 1) == 0) {
                    acc[l] = fma2(w0,  E[ci][l/2 - 1], acc[l]);
                    acc[l] = fma2(w12, E[ci][l/2],     acc[l]);
                } else {
                    acc[l] = fma2(w01, E[ci][(l-1)/2], acc[l]);
                    acc[l] = fma2(w2,  E[ci][(l+1)/2], acc[l]);
                }
            }
            acc[15] = fma2(w01, E[ci][7], acc[15]);
        }
        #pragma unroll
        for (int l = 0; l < 16; l++)
            O2[c*16 + l] = tanh2(acc[l]);
    }

    // ---- store: unpack, one 128B line per sample ----
    {
        float4* op = out + (size_t)i * 16;
        #pragma unroll
        for (int q = 0; q < 8; q++) {
            float4 va, vb;
            upk(O2[q*4+0], va.x, vb.x);
            upk(O2[q*4+1], va.y, vb.y);
            upk(O2[q*4+2], va.z, vb.z);
            upk(O2[q*4+3], va.w, vb.w);
            op[q]     = va;
            op[8 + q] = vb;
        }
    }
}

extern "C" void kernel_launch(void* const* d_in, const int* in_sizes, int n_in,
                              void* d_out, int out_size) {
    const float4* x      = (const float4*)d_in[0];
    const float* w_enc1  = (const float*)d_in[1];
    const float* b_enc1  = (const float*)d_in[2];
    const float* w_bneck = (const float*)d_in[3];
    const float* b_bneck = (const float*)d_in[4];
    const float* w_dec1  = (const float*)d_in[5];
    const float* b_dec1  = (const float*)d_in[6];
    const float* w_out   = (const float*)d_in[7];
    const float* b_out   = (const float*)d_in[8];
    float4* out = (float4*)d_out;

    int B = in_sizes[0] / 32;        // samples
    int pairs = B / 2;               // two samples per thread
    int threads = 128;
    int blocks = (pairs + threads - 1) / threads;
    minigen_kernel<<<blocks, threads>>>(x, w_enc1, b_enc1, w_bneck, b_bneck,
                                        w_dec1, b_dec1, w_out, b_out, out);
}